// round 4
// baseline (speedup 1.0000x reference)
#include <cuda_runtime.h>
#include <cstdint>

#define MAX_SEGS 65536
__device__ int g_starts[MAX_SEGS];   // absolute exclusive prefix of obj_size

// ---------------------------------------------------------------------------
// K1: single-block exclusive scan, coalesced multi-pass.
// grid=1, block=1024. Pass p handles indices [p*1024, p*1024+1024) with a
// carried running offset. Each pass: warp shfl scan -> warp-total scan ->
// absolute starts. ~16 passes for n=16384.
// ---------------------------------------------------------------------------
__global__ void scan_kernel(const int* __restrict__ sz, int n) {
    __shared__ int s_tot[32];   // per-warp inclusive totals
    __shared__ int s_off[32];   // per-warp exclusive offsets
    __shared__ int s_carry;     // running offset across passes

    const int t    = threadIdx.x;
    const int lane = t & 31;
    const int wid  = t >> 5;

    if (t == 0) s_carry = 0;
    __syncthreads();

    const int npass = (n + 1023) >> 10;
    for (int p = 0; p < npass; ++p) {
        const int idx = (p << 10) + t;
        int v = (idx < n) ? sz[idx] : 0;

        // warp inclusive scan
        int inc = v;
        #pragma unroll
        for (int d = 1; d < 32; d <<= 1) {
            int u = __shfl_up_sync(0xFFFFFFFFu, inc, d);
            if (lane >= d) inc += u;
        }
        if (lane == 31) s_tot[wid] = inc;
        __syncthreads();

        // warp 0 scans the 32 warp totals
        int carry = s_carry;
        if (wid == 0) {
            int wv = s_tot[lane];
            int winc = wv;
            #pragma unroll
            for (int d = 1; d < 32; d <<= 1) {
                int u = __shfl_up_sync(0xFFFFFFFFu, winc, d);
                if (lane >= d) winc += u;
            }
            s_off[lane] = winc - wv;                 // exclusive warp offset
            if (lane == 31) s_carry = carry + winc;  // pass total folded in
        }
        __syncthreads();

        if (idx < n) g_starts[idx] = carry + s_off[wid] + (inc - v);
    }
}

// ---------------------------------------------------------------------------
// K2: one CTA per segment. 128 threads = 4 warps.
// Lane l owns float4-column l; warps stride rows by 4.
// Fast path for len==64 with MLP=8 streaming loads.
// ---------------------------------------------------------------------------
__global__ __launch_bounds__(128)
void seg_mean_kernel(const float* __restrict__ data,
                     const int* __restrict__ sz,
                     float* __restrict__ out) {
    const int seg = blockIdx.x;
    const int t = threadIdx.x;
    const int w = t >> 5;
    const int l = t & 31;

    const int start = g_starts[seg];
    const int len   = sz[seg];

    const float4* __restrict__ base =
        reinterpret_cast<const float4*>(data) + (size_t)start * 32 + l;

    float4 acc = make_float4(0.f, 0.f, 0.f, 0.f);

    if (len == 64) {
        #pragma unroll
        for (int b = 0; b < 2; ++b) {
            float4 v[8];
            #pragma unroll
            for (int i = 0; i < 8; ++i)
                v[i] = __ldcs(&base[(size_t)(w + (b * 8 + i) * 4) * 32]);
            #pragma unroll
            for (int i = 0; i < 8; ++i) {
                acc.x += v[i].x; acc.y += v[i].y;
                acc.z += v[i].z; acc.w += v[i].w;
            }
        }
    } else {
        int r = w;
        for (; r + 12 < len; r += 16) {
            float4 v0 = __ldcs(&base[(size_t)(r     ) * 32]);
            float4 v1 = __ldcs(&base[(size_t)(r +  4) * 32]);
            float4 v2 = __ldcs(&base[(size_t)(r +  8) * 32]);
            float4 v3 = __ldcs(&base[(size_t)(r + 12) * 32]);
            acc.x += v0.x + v1.x + v2.x + v3.x;
            acc.y += v0.y + v1.y + v2.y + v3.y;
            acc.z += v0.z + v1.z + v2.z + v3.z;
            acc.w += v0.w + v1.w + v2.w + v3.w;
        }
        for (; r < len; r += 4) {
            float4 v = __ldcs(&base[(size_t)r * 32]);
            acc.x += v.x; acc.y += v.y; acc.z += v.z; acc.w += v.w;
        }
    }

    __shared__ float4 sm[4][32];
    sm[w][l] = acc;
    __syncthreads();

    if (w == 0) {
        float4 a = sm[0][l];
        float4 b = sm[1][l];
        float4 c = sm[2][l];
        float4 d = sm[3][l];
        const float inv = (len > 0) ? (1.0f / (float)len) : 0.0f;
        float4 o;
        o.x = (a.x + b.x + c.x + d.x) * inv;
        o.y = (a.y + b.y + c.y + d.y) * inv;
        o.z = (a.z + b.z + c.z + d.z) * inv;
        o.w = (a.w + b.w + c.w + d.w) * inv;
        __stcs(&reinterpret_cast<float4*>(out)[(size_t)seg * 32 + l], o);
    }
}

// ---------------------------------------------------------------------------
// kernel_launch
// ---------------------------------------------------------------------------
extern "C" void kernel_launch(void* const* d_in, const int* in_sizes, int n_in,
                              void* d_out, int out_size) {
    const float* data = (const float*)d_in[0];
    const int*   sz   = (const int*)d_in[1];
    float*       out  = (float*)d_out;
    const int n_seg = in_sizes[1];

    scan_kernel<<<1, 1024>>>(sz, n_seg);
    seg_mean_kernel<<<n_seg, 128>>>(data, sz, out);
}

// round 5
// speedup vs baseline: 1.0007x; 1.0007x over previous
#include <cuda_runtime.h>
#include <cstdint>

#define MAX_SEGS 65536
__device__ int g_starts[MAX_SEGS];   // absolute exclusive prefix of obj_size

// ---------------------------------------------------------------------------
// K1: single-block exclusive scan with register prefetch.
// grid=1, block=1024. Thread t prefetches sz[p*1024+t] for all passes p
// (coalesced, MLP up to 16), then runs the carry-serial scan from registers.
// Ends with griddepcontrol.launch_dependents so the PDL-launched seg_mean
// may proceed past its griddepcontrol.wait.
// ---------------------------------------------------------------------------
__global__ void scan_kernel(const int* __restrict__ sz, int n) {
    __shared__ int s_tot[32];
    __shared__ int s_off[32];
    __shared__ int s_carry;

    const int t    = threadIdx.x;
    const int lane = t & 31;
    const int wid  = t >> 5;
    const int npass = (n + 1023) >> 10;

    if (t == 0) s_carry = 0;

    // Prefetch all values (coalesced across the block, deep MLP).
    int vals[16];
    if (npass <= 16) {
        #pragma unroll
        for (int p = 0; p < 16; ++p) {
            const int idx = (p << 10) + t;
            vals[p] = (p < npass && idx < n) ? sz[idx] : 0;
        }
    }
    __syncthreads();

    for (int p = 0; p < npass; ++p) {
        const int idx = (p << 10) + t;
        int v;
        if (npass <= 16) v = vals[p];
        else             v = (idx < n) ? sz[idx] : 0;

        // warp inclusive scan
        int inc = v;
        #pragma unroll
        for (int d = 1; d < 32; d <<= 1) {
            int u = __shfl_up_sync(0xFFFFFFFFu, inc, d);
            if (lane >= d) inc += u;
        }
        if (lane == 31) s_tot[wid] = inc;
        __syncthreads();

        int carry = s_carry;
        if (wid == 0) {
            int wv = s_tot[lane];
            int winc = wv;
            #pragma unroll
            for (int d = 1; d < 32; d <<= 1) {
                int u = __shfl_up_sync(0xFFFFFFFFu, winc, d);
                if (lane >= d) winc += u;
            }
            s_off[lane] = winc - wv;
            if (lane == 31) s_carry = carry + winc;
        }
        __syncthreads();

        if (idx < n) g_starts[idx] = carry + s_off[wid] + (inc - v);
    }

    __syncthreads();
    // All g_starts stores done -> release dependent grid.
    asm volatile("griddepcontrol.launch_dependents;" ::: "memory");
}

// ---------------------------------------------------------------------------
// K2: one CTA per segment. 128 threads = 4 warps. PDL dependent:
// loads len early, waits for scan, then reads its start offset.
// Hot loop unchanged from the proven 80us/85%-DRAM version.
// ---------------------------------------------------------------------------
__global__ __launch_bounds__(128)
void seg_mean_kernel(const float* __restrict__ data,
                     const int* __restrict__ sz,
                     float* __restrict__ out) {
    const int seg = blockIdx.x;
    const int t = threadIdx.x;
    const int w = t >> 5;
    const int l = t & 31;

    const int len = sz[seg];            // independent of scan: issue early

    asm volatile("griddepcontrol.wait;" ::: "memory");

    const int start = g_starts[seg];

    const float4* __restrict__ base =
        reinterpret_cast<const float4*>(data) + (size_t)start * 32 + l;

    float4 acc = make_float4(0.f, 0.f, 0.f, 0.f);

    if (len == 64) {
        #pragma unroll
        for (int b = 0; b < 2; ++b) {
            float4 v[8];
            #pragma unroll
            for (int i = 0; i < 8; ++i)
                v[i] = __ldcs(&base[(size_t)(w + (b * 8 + i) * 4) * 32]);
            #pragma unroll
            for (int i = 0; i < 8; ++i) {
                acc.x += v[i].x; acc.y += v[i].y;
                acc.z += v[i].z; acc.w += v[i].w;
            }
        }
    } else {
        int r = w;
        for (; r + 12 < len; r += 16) {
            float4 v0 = __ldcs(&base[(size_t)(r     ) * 32]);
            float4 v1 = __ldcs(&base[(size_t)(r +  4) * 32]);
            float4 v2 = __ldcs(&base[(size_t)(r +  8) * 32]);
            float4 v3 = __ldcs(&base[(size_t)(r + 12) * 32]);
            acc.x += v0.x + v1.x + v2.x + v3.x;
            acc.y += v0.y + v1.y + v2.y + v3.y;
            acc.z += v0.z + v1.z + v2.z + v3.z;
            acc.w += v0.w + v1.w + v2.w + v3.w;
        }
        for (; r < len; r += 4) {
            float4 v = __ldcs(&base[(size_t)r * 32]);
            acc.x += v.x; acc.y += v.y; acc.z += v.z; acc.w += v.w;
        }
    }

    __shared__ float4 sm[4][32];
    sm[w][l] = acc;
    __syncthreads();

    if (w == 0) {
        float4 a = sm[0][l];
        float4 b = sm[1][l];
        float4 c = sm[2][l];
        float4 d = sm[3][l];
        const float inv = (len > 0) ? (1.0f / (float)len) : 0.0f;
        float4 o;
        o.x = (a.x + b.x + c.x + d.x) * inv;
        o.y = (a.y + b.y + c.y + d.y) * inv;
        o.z = (a.z + b.z + c.z + d.z) * inv;
        o.w = (a.w + b.w + c.w + d.w) * inv;
        __stcs(&reinterpret_cast<float4*>(out)[(size_t)seg * 32 + l], o);
    }
}

// ---------------------------------------------------------------------------
// kernel_launch: scan, then PDL-overlapped seg_mean.
// ---------------------------------------------------------------------------
extern "C" void kernel_launch(void* const* d_in, const int* in_sizes, int n_in,
                              void* d_out, int out_size) {
    const float* data = (const float*)d_in[0];
    const int*   sz   = (const int*)d_in[1];
    float*       out  = (float*)d_out;
    const int n_seg = in_sizes[1];

    scan_kernel<<<1, 1024>>>(sz, n_seg);

    cudaLaunchConfig_t cfg = {};
    cfg.gridDim  = dim3((unsigned)n_seg, 1, 1);
    cfg.blockDim = dim3(128, 1, 1);
    cfg.dynamicSmemBytes = 0;
    cfg.stream = 0;   // legacy default stream (same as <<<>>>), capture-safe

    cudaLaunchAttribute attrs[1];
    attrs[0].id = cudaLaunchAttributeProgrammaticStreamSerialization;
    attrs[0].val.programmaticStreamSerializationAllowed = 1;
    cfg.attrs = attrs;
    cfg.numAttrs = 1;

    cudaLaunchKernelEx(&cfg, seg_mean_kernel, data, sz, out);
}